// round 17
// baseline (speedup 1.0000x reference)
#include <cuda_runtime.h>

// LinearActorNet: B=2048, K=512, N=256, T=64. task_id/action int32.
// out layout (float32): [action(B) | log_prob(B) | entropy(B)]
//
// 2-kernel pipeline:
//  1) setup:  64 CTAs x 256 thr, register-cached ballot compaction (once).
//  2) logits: grid (64 tasks x 4 slots x 4 K-quarters), 256 thr, TMR=16,
//     thread = (row-group, col pair): 8 rows x 2 cols x 128 k, depth-2
//     register double-buffer on the W stream. After storing partials, the
//     LAST of the 4 K-quarter CTAs for each (task,tile) runs the fused
//     log-softmax epilogue in-place (threadfence + arrival counter) —
//     no separate softmax kernel, partials consumed L2-hot.

#define BB 2048
#define KK 512
#define NN 256
#define TT 64
#define TMR 16
#define NSLOT 4
#define KSPLIT 4
#define KH 128
#define LSTRIDE 128
#define MAXTILE (LSTRIDE / TMR)   // 8

__device__ unsigned short g_list[TT * LSTRIDE];
__device__ int g_cnt[TT];
__device__ float g_part[KSPLIT][BB][NN];
__device__ int g_arrive[TT * MAXTILE];   // zero-init; reset by epilogue CTA

union f2u { float2 f; unsigned long long u; };
__device__ __forceinline__ unsigned long long pk(float lo, float hi) {
    f2u u; u.f = make_float2(lo, hi); return u.u;
}
__device__ __forceinline__ float fold(unsigned long long v) {
    f2u u; u.u = v; return u.f.x + u.f.y;
}
#define FFMA2(d, a, b) \
    asm("fma.rn.f32x2 %0, %1, %2, %0;" : "+l"(d) : "l"(a), "l"(b))

// ---------------- setup: per-task parallel compaction ----------------
__global__ __launch_bounds__(256, 4)
void setup_kernel(const int* __restrict__ task_id)
{
    const int t    = blockIdx.x;
    const int lane = threadIdx.x & 31;
    const int w    = threadIdx.x >> 5;          // 0..7
    const unsigned lt = (1u << lane) - 1u;
    __shared__ int wcnt[8];

    int ids[8];
    #pragma unroll
    for (int i = 0; i < 8; i++)
        ids[i] = task_id[w * 256 + i * 32 + lane];

    int c = 0;
    #pragma unroll
    for (int i = 0; i < 8; i++)
        c += __popc(__ballot_sync(0xffffffffu, ids[i] == t));
    if (lane == 0) wcnt[w] = c;
    __syncthreads();
    int base = 0;
    #pragma unroll
    for (int i = 0; i < 8; i++) if (i < w) base += wcnt[i];
    if (w == 7 && lane == 0) g_cnt[t] = base + wcnt[7];

    #pragma unroll
    for (int i = 0; i < 8; i++) {
        bool p = (ids[i] == t);
        unsigned m = __ballot_sync(0xffffffffu, p);
        if (p) {
            int pos = base + __popc(m & lt);
            if (pos < LSTRIDE)
                g_list[t * LSTRIDE + pos] =
                    (unsigned short)(w * 256 + i * 32 + lane);
        }
        base += __popc(m);
    }
}

// ---------------- logits + in-place fused softmax ----------------
#define LOADW(d, p) do {                                              \
    const float* _wk = (p);                                           \
    d##0 = _wk[0];    d##1 = _wk[NN];     d##2 = _wk[2*NN];   d##3 = _wk[3*NN];   \
    d##4 = _wk[128];  d##5 = _wk[NN+128]; d##6 = _wk[2*NN+128]; d##7 = _wk[3*NN+128]; \
} while (0)

#define FMABLK(d, kk) do {                                            \
    unsigned long long wA0 = pk(d##0, d##1), wA1 = pk(d##2, d##3);    \
    unsigned long long wB0 = pk(d##4, d##5), wB1 = pk(d##6, d##7);    \
    _Pragma("unroll")                                                 \
    for (int m = 0; m < 8; m++) {                                     \
        ulonglong2 xv = *(const ulonglong2*)&xs_s[rg * 8 + m][kk];    \
        FFMA2(acc0[m], xv.x, wA0);                                    \
        FFMA2(acc0[m], xv.y, wA1);                                    \
        FFMA2(acc1[m], xv.x, wB0);                                    \
        FFMA2(acc1[m], xv.y, wB1);                                    \
    }                                                                 \
} while (0)

__global__ __launch_bounds__(256, 3)
void logits_kernel(const float* __restrict__ xs,
                   const int* __restrict__ action,
                   const float* __restrict__ W,
                   const float* __restrict__ bias,
                   float* __restrict__ out)
{
    __shared__ float xs_s[TMR][KH];              // 8 KB
    __shared__ float bias_s[NN];
    __shared__ int last_flag;

    const int tid  = threadIdx.x;
    const int t    = blockIdx.x;
    const int slot = blockIdx.y;
    const int ks   = blockIdx.z;
    const int lane = tid & 31;
    const int w    = tid >> 5;

    const int cnt = min(g_cnt[t], LSTRIDE);
    if (slot * TMR >= cnt) return;
    const unsigned short* __restrict__ lst = g_list + t * LSTRIDE;

    bias_s[tid] = bias[t * NN + tid];

    const int rg = tid >> 7;                     // rows rg*8 .. rg*8+7
    const int cl = tid & 127;                    // cols cl, cl+128
    const float* __restrict__ Wt =
        W + (size_t)t * (KK * NN) + (size_t)ks * KH * NN + cl;

    for (int tile = slot; tile * TMR < cnt; tile += NSLOT) {
        const int m0 = tile * TMR;
        const int mc = min(TMR, cnt - m0);
        __syncthreads();

        // ---- stage xs tile [TMR][KH] (float4, coalesced) ----
        #pragma unroll
        for (int i = 0; i < (TMR * KH / 4) / 256; i++) {   // 2 iters
            int idx = i * 256 + tid;
            int m = idx >> 5;                              // 32 float4 per row
            int cc = idx & 31;
            float4 v = make_float4(0.f, 0.f, 0.f, 0.f);
            if (m < mc) {
                const float4* src =
                    (const float4*)(xs + (size_t)lst[m0 + m] * KK + ks * KH);
                v = src[cc];
            }
            *(float4*)&xs_s[m][cc * 4] = v;
        }
        __syncthreads();

        // ---- GEMM, depth-2 register double-buffer on W ----
        unsigned long long acc0[8], acc1[8];
        #pragma unroll
        for (int m = 0; m < 8; m++) { acc0[m] = 0ull; acc1[m] = 0ull; }

        float A0, A1, A2, A3, A4, A5, A6, A7;
        float B0, B1, B2, B3, B4, B5, B6, B7;
        LOADW(A, Wt);
        #pragma unroll
        for (int k = 0; k < KH; k += 8) {
            LOADW(B, Wt + (size_t)(k + 4) * NN);           // prefetch
            FMABLK(A, k);
            if (k + 8 < KH) LOADW(A, Wt + (size_t)(k + 8) * NN);
            FMABLK(B, k + 4);
        }

        // ---- store partials (coalesced) ----
        #pragma unroll
        for (int m = 0; m < 8; m++) {
            int r = rg * 8 + m;
            if (r < mc) {
                float* dst = &g_part[ks][lst[m0 + r]][0];
                dst[cl]       = fold(acc0[m]);
                dst[cl + 128] = fold(acc1[m]);
            }
        }

        // ---- arrival: last of the 4 ks-CTAs runs the epilogue ----
        __threadfence();
        __syncthreads();
        if (tid == 0) {
            int old = atomicAdd(&g_arrive[t * MAXTILE + tile], 1);
            last_flag = (old == KSPLIT - 1);
        }
        __syncthreads();

        if (last_flag) {
            __threadfence();
            if (tid == 0) g_arrive[t * MAXTILE + tile] = 0;  // reset for replay

            // warps 0..7 -> rows 2w, 2w+1 of this tile
            #pragma unroll
            for (int rr = 0; rr < 2; rr++) {
                const int r = w * 2 + rr;
                if (r >= mc) continue;
                const int gb = lst[m0 + r];
                const int a  = action[gb];

                float vr[8];
                #pragma unroll
                for (int j = 0; j < 8; j++) {
                    int cc = j * 32 + lane;
                    vr[j] = (g_part[0][gb][cc] + g_part[1][gb][cc])
                          + (g_part[2][gb][cc] + g_part[3][gb][cc])
                          + bias_s[cc];
                }
                float mx = vr[0];
                #pragma unroll
                for (int j = 1; j < 8; j++) mx = fmaxf(mx, vr[j]);
                #pragma unroll
                for (int o = 16; o > 0; o >>= 1)
                    mx = fmaxf(mx, __shfl_xor_sync(0xffffffffu, mx, o));

                float s1 = 0.f, s2 = 0.f, s3 = 0.f;
                #pragma unroll
                for (int j = 0; j < 8; j++) {
                    int cc = j * 32 + lane;
                    float d = vr[j] - mx;
                    float e = __expf(d);
                    s1 += e; s2 += e * d;
                    if (cc == a) s3 += vr[j];
                }
                #pragma unroll
                for (int o = 16; o > 0; o >>= 1) {
                    s1 += __shfl_xor_sync(0xffffffffu, s1, o);
                    s2 += __shfl_xor_sync(0xffffffffu, s2, o);
                    s3 += __shfl_xor_sync(0xffffffffu, s3, o);
                }
                if (lane == 0) {
                    float logS = logf(s1);
                    out[gb]          = (float)a;               // action
                    out[BB + gb]     = s3 - mx - logS;         // log_prob
                    out[2 * BB + gb] = logS - s2 / s1;         // entropy
                }
            }
        }
    }
}

extern "C" void kernel_launch(void* const* d_in, const int* in_sizes, int n_in,
                              void* d_out, int out_size) {
    const float* xs      = (const float*)d_in[0];
    const int*   task_id = (const int*)d_in[1];
    const int*   action  = (const int*)d_in[2];
    const float* W       = (const float*)d_in[3];
    const float* bias    = (const float*)d_in[4];
    float*       out     = (float*)d_out;

    setup_kernel<<<TT, 256>>>(task_id);
    dim3 grid(TT, NSLOT, KSPLIT);
    logits_kernel<<<grid, 256>>>(xs, action, W, bias, out);
}